// round 1
// baseline (speedup 1.0000x reference)
#include <cuda_runtime.h>
#include <cuda_bf16.h>
#include <math.h>

// Problem constants
#define BB   4
#define SS   1024
#define HID  1024
#define NH   16
#define HD   64
#define NPOS 73          // LEFT(64)+RIGHT(8)+1
#define MTOT (BB*SS)     // 4096
#define BHT  (BB*NH)     // 64

// Scratch (static device globals; no runtime allocation)
__device__ float g_q[MTOT * HID];            // [B,NH,S,HD]
__device__ float g_k[MTOT * HID];
__device__ float g_v[MTOT * HID];
__device__ float g_ctx[MTOT * HID];          // [B,S,HID]
__device__ float g_qd[(size_t)BHT * SS * NPOS];

// ---------------------------------------------------------------------------
// NT GEMM: C[m,n] = sum_k A[m,k]*W[n,k] + bias[n].  M=4096,N=1024,K=1024.
// permute=1: write to [B,NH,S,HD] layout (for q/k/v); permute=0: row-major.
// ---------------------------------------------------------------------------
__global__ __launch_bounds__(256) void gemm_nt_1024(
    const float* __restrict__ A, const float* __restrict__ W,
    const float* __restrict__ bias, float* __restrict__ out, int permute)
{
    const int K = 1024;
    __shared__ float As[16][132];
    __shared__ float Bs[16][132];
    float c[8][8];
#pragma unroll
    for (int i = 0; i < 8; i++)
#pragma unroll
        for (int j = 0; j < 8; j++) c[i][j] = 0.f;

    int tid = threadIdx.x;
    int m0 = blockIdx.y * 128, n0 = blockIdx.x * 128;
    int tm = (tid >> 4) << 3, tn = (tid & 15) << 3;

    for (int k0 = 0; k0 < K; k0 += 16) {
#pragma unroll
        for (int i = 0; i < 2; i++) {
            int v  = tid + i * 256;
            int m  = v >> 2;
            int kq = (v & 3) << 2;
            float4 a = *reinterpret_cast<const float4*>(A + (size_t)(m0 + m) * K + k0 + kq);
            As[kq + 0][m] = a.x; As[kq + 1][m] = a.y; As[kq + 2][m] = a.z; As[kq + 3][m] = a.w;
            float4 b = *reinterpret_cast<const float4*>(W + (size_t)(n0 + m) * K + k0 + kq);
            Bs[kq + 0][m] = b.x; Bs[kq + 1][m] = b.y; Bs[kq + 2][m] = b.z; Bs[kq + 3][m] = b.w;
        }
        __syncthreads();
#pragma unroll
        for (int kk = 0; kk < 16; kk++) {
            float a[8], b[8];
#pragma unroll
            for (int j = 0; j < 8; j++) { a[j] = As[kk][tm + j]; b[j] = Bs[kk][tn + j]; }
#pragma unroll
            for (int i = 0; i < 8; i++)
#pragma unroll
                for (int j = 0; j < 8; j++) c[i][j] = fmaf(a[i], b[j], c[i][j]);
        }
        __syncthreads();
    }

#pragma unroll
    for (int i = 0; i < 8; i++) {
        int m = m0 + tm + i;
#pragma unroll
        for (int j = 0; j < 8; j++) {
            int n = n0 + tn + j;
            float val = c[i][j] + bias[n];
            if (permute) {
                int b = m >> 10, l = m & 1023, h = n >> 6, d = n & 63;
                out[(((size_t)(b * NH + h) << 10) + l) * HD + d] = val;
            } else {
                out[(size_t)m * 1024 + n] = val;
            }
        }
    }
}

// ---------------------------------------------------------------------------
// qd[row,p] = (1/8) * sum_d q[row,d] * dist_emb[p,d]  (row = bh*S + l)
// ---------------------------------------------------------------------------
__global__ __launch_bounds__(256) void qd_kernel(
    const float* __restrict__ q, const float* __restrict__ emb, float* __restrict__ qd)
{
    __shared__ float semb[NPOS][65];
    for (int i = threadIdx.x; i < NPOS * HD; i += 256)
        semb[i / HD][i % HD] = emb[i];
    __syncthreads();

    size_t idx = (size_t)blockIdx.x * 256 + threadIdx.x;
    const size_t total = (size_t)BHT * SS * NPOS;
    if (idx >= total) return;
    int p = (int)(idx % NPOS);
    size_t row = idx / NPOS;
    const float* qr = q + row * HD;
    float s = 0.f;
#pragma unroll
    for (int d = 0; d < HD; d++) s = fmaf(qr[d], semb[p][d], s);
    qd[idx] = s * 0.125f;
}

// ---------------------------------------------------------------------------
// scores[bh,l,r] = (q.k)/8 + qd[bh,l,clip(r-l,-64,8)+64], written pre-softmax
// ---------------------------------------------------------------------------
__global__ __launch_bounds__(256) void scores_kernel(
    const float* __restrict__ q, const float* __restrict__ k,
    const float* __restrict__ qd, float* __restrict__ probs)
{
    int bh = blockIdx.z;
    const float* A  = q + (size_t)bh * SS * HD;
    const float* Bp = k + (size_t)bh * SS * HD;

    __shared__ float As[16][132];
    __shared__ float Bs[16][132];
    float c[8][8];
#pragma unroll
    for (int i = 0; i < 8; i++)
#pragma unroll
        for (int j = 0; j < 8; j++) c[i][j] = 0.f;

    int tid = threadIdx.x;
    int m0 = blockIdx.y * 128, n0 = blockIdx.x * 128;
    int tm = (tid >> 4) << 3, tn = (tid & 15) << 3;

    for (int k0 = 0; k0 < HD; k0 += 16) {
#pragma unroll
        for (int i = 0; i < 2; i++) {
            int v  = tid + i * 256;
            int m  = v >> 2;
            int kq = (v & 3) << 2;
            float4 a = *reinterpret_cast<const float4*>(A + (size_t)(m0 + m) * HD + k0 + kq);
            As[kq + 0][m] = a.x; As[kq + 1][m] = a.y; As[kq + 2][m] = a.z; As[kq + 3][m] = a.w;
            float4 b = *reinterpret_cast<const float4*>(Bp + (size_t)(n0 + m) * HD + k0 + kq);
            Bs[kq + 0][m] = b.x; Bs[kq + 1][m] = b.y; Bs[kq + 2][m] = b.z; Bs[kq + 3][m] = b.w;
        }
        __syncthreads();
#pragma unroll
        for (int kk = 0; kk < 16; kk++) {
            float a[8], b[8];
#pragma unroll
            for (int j = 0; j < 8; j++) { a[j] = As[kk][tm + j]; b[j] = Bs[kk][tn + j]; }
#pragma unroll
            for (int i = 0; i < 8; i++)
#pragma unroll
                for (int j = 0; j < 8; j++) c[i][j] = fmaf(a[i], b[j], c[i][j]);
        }
        __syncthreads();
    }

    const float* qdrow = qd + ((size_t)bh * SS) * NPOS;
#pragma unroll
    for (int i = 0; i < 8; i++) {
        int l = m0 + tm + i;
#pragma unroll
        for (int j = 0; j < 8; j++) {
            int r = n0 + tn + j;
            int dist = r - l;
            dist = min(max(dist, -64), 8) + 64;
            float val = c[i][j] * 0.125f + qdrow[(size_t)l * NPOS + dist];
            probs[(((size_t)bh << 10) + l) * SS + r] = val;
        }
    }
}

// ---------------------------------------------------------------------------
// In-place row softmax over 1024 columns. One block per row.
// ---------------------------------------------------------------------------
__global__ __launch_bounds__(256) void softmax_kernel(float* __restrict__ probs)
{
    size_t row = blockIdx.x;
    float* p = probs + row * SS;
    int tid = threadIdx.x;
    float4 v = *reinterpret_cast<float4*>(p + tid * 4);

    float mx = fmaxf(fmaxf(v.x, v.y), fmaxf(v.z, v.w));
#pragma unroll
    for (int o = 16; o; o >>= 1) mx = fmaxf(mx, __shfl_xor_sync(0xffffffffu, mx, o));
    __shared__ float red[8];
    if ((tid & 31) == 0) red[tid >> 5] = mx;
    __syncthreads();
    mx = red[0];
#pragma unroll
    for (int w = 1; w < 8; w++) mx = fmaxf(mx, red[w]);
    __syncthreads();

    v.x = __expf(v.x - mx); v.y = __expf(v.y - mx);
    v.z = __expf(v.z - mx); v.w = __expf(v.w - mx);
    float s = v.x + v.y + v.z + v.w;
#pragma unroll
    for (int o = 16; o; o >>= 1) s += __shfl_xor_sync(0xffffffffu, s, o);
    if ((tid & 31) == 0) red[tid >> 5] = s;
    __syncthreads();
    s = red[0];
#pragma unroll
    for (int w = 1; w < 8; w++) s += red[w];

    float inv = 1.0f / s;
    v.x *= inv; v.y *= inv; v.z *= inv; v.w *= inv;
    *reinterpret_cast<float4*>(p + tid * 4) = v;
}

// ---------------------------------------------------------------------------
// ctx[b,l,h*64+d] = sum_r probs[bh,l,r] * v[bh,r,d]
// ---------------------------------------------------------------------------
__global__ __launch_bounds__(256) void pv_kernel(
    const float* __restrict__ P, const float* __restrict__ V, float* __restrict__ ctx)
{
    int bh = blockIdx.y;
    const float* A  = P + (size_t)bh * SS * SS;
    const float* Bv = V + (size_t)bh * SS * HD;

    __shared__ float As[16][132];
    __shared__ float Bs[16][68];
    float c[8][4];
#pragma unroll
    for (int i = 0; i < 8; i++)
#pragma unroll
        for (int j = 0; j < 4; j++) c[i][j] = 0.f;

    int tid = threadIdx.x;
    int m0 = blockIdx.x * 128;
    int tm = (tid >> 4) << 3, tn = (tid & 15) << 2;

    for (int k0 = 0; k0 < SS; k0 += 16) {
#pragma unroll
        for (int i = 0; i < 2; i++) {
            int v  = tid + i * 256;
            int m  = v >> 2;
            int kq = (v & 3) << 2;
            float4 a = *reinterpret_cast<const float4*>(A + (size_t)(m0 + m) * SS + k0 + kq);
            As[kq + 0][m] = a.x; As[kq + 1][m] = a.y; As[kq + 2][m] = a.z; As[kq + 3][m] = a.w;
        }
        {
            int kk = tid >> 4, nq = (tid & 15) << 2;
            float4 b = *reinterpret_cast<const float4*>(Bv + (size_t)(k0 + kk) * HD + nq);
            Bs[kk][nq + 0] = b.x; Bs[kk][nq + 1] = b.y; Bs[kk][nq + 2] = b.z; Bs[kk][nq + 3] = b.w;
        }
        __syncthreads();
#pragma unroll
        for (int kk = 0; kk < 16; kk++) {
            float a[8], b[4];
#pragma unroll
            for (int i = 0; i < 8; i++) a[i] = As[kk][tm + i];
#pragma unroll
            for (int j = 0; j < 4; j++) b[j] = Bs[kk][tn + j];
#pragma unroll
            for (int i = 0; i < 8; i++)
#pragma unroll
                for (int j = 0; j < 4; j++) c[i][j] = fmaf(a[i], b[j], c[i][j]);
        }
        __syncthreads();
    }

    int b_ = bh >> 4, h = bh & 15;
#pragma unroll
    for (int i = 0; i < 8; i++) {
        int l = m0 + tm + i;
#pragma unroll
        for (int j = 0; j < 4; j++) {
            ctx[((size_t)(b_ << 10) + l) * HID + (h << 6) + tn + j] = c[i][j];
        }
    }
}

// ---------------------------------------------------------------------------
extern "C" void kernel_launch(void* const* d_in, const int* in_sizes, int n_in,
                              void* d_out, int out_size)
{
    const float* hid  = (const float*)d_in[0];
    const float* Wq   = (const float*)d_in[1];
    const float* bq   = (const float*)d_in[2];
    const float* Wk   = (const float*)d_in[3];
    const float* bk   = (const float*)d_in[4];
    const float* Wv   = (const float*)d_in[5];
    const float* bv   = (const float*)d_in[6];
    const float* Wo   = (const float*)d_in[7];
    const float* bo   = (const float*)d_in[8];
    const float* demb = (const float*)d_in[9];

    float* out   = (float*)d_out;                       // [B,S,HID]
    float* probs = out + (size_t)MTOT * HID;            // [B,NH,S,S]

    float *q, *k, *v, *ctx, *qd;
    cudaGetSymbolAddress((void**)&q,   g_q);
    cudaGetSymbolAddress((void**)&k,   g_k);
    cudaGetSymbolAddress((void**)&v,   g_v);
    cudaGetSymbolAddress((void**)&ctx, g_ctx);
    cudaGetSymbolAddress((void**)&qd,  g_qd);

    dim3 gproj(8, 32);
    gemm_nt_1024<<<gproj, 256>>>(hid, Wq, bq, q, 1);
    gemm_nt_1024<<<gproj, 256>>>(hid, Wk, bk, k, 1);
    gemm_nt_1024<<<gproj, 256>>>(hid, Wv, bv, v, 1);

    qd_kernel<<<(BHT * SS * NPOS + 255) / 256, 256>>>(q, demb, qd);

    dim3 gs(8, 8, BHT);
    scores_kernel<<<gs, 256>>>(q, k, qd, probs);

    softmax_kernel<<<BHT * SS, 256>>>(probs);

    dim3 gp(8, BHT);
    pv_kernel<<<gp, 256>>>(probs, v, ctx);

    gemm_nt_1024<<<gproj, 256>>>(ctx, Wo, bo, out, 0);
}

// round 3
// speedup vs baseline: 1.9389x; 1.9389x over previous
#include <cuda_runtime.h>
#include <cuda_bf16.h>
#include <math.h>
#include <stdint.h>

#define BB   4
#define SS   1024
#define HIDN 1024
#define NHH  16
#define HDD  64
#define NPOS 73
#define MTOT 4096
#define BHT  64

// Scratch
__device__ float g_q[MTOT * HIDN];            // [bh, l, d]
__device__ float g_k[MTOT * HIDN];            // [bh, l, d]
__device__ float g_v[MTOT * HIDN];            // vT: [bh, d, r]
__device__ float g_ctx[MTOT * HIDN];          // [b, l, hid]
__device__ float g_qd[(size_t)BHT * SS * NPOS];

__device__ __forceinline__ uint32_t f2tf32(float x) {
    uint32_t u; asm("cvt.rna.tf32.f32 %0, %1;" : "=r"(u) : "f"(x)); return u;
}

__device__ __forceinline__ void mma8(float* c, const uint32_t* a, const uint32_t* b) {
    asm volatile(
        "mma.sync.aligned.m16n8k8.row.col.f32.tf32.tf32.f32 "
        "{%0,%1,%2,%3}, {%4,%5,%6,%7}, {%8,%9}, {%0,%1,%2,%3};"
        : "+f"(c[0]), "+f"(c[1]), "+f"(c[2]), "+f"(c[3])
        : "r"(a[0]), "r"(a[1]), "r"(a[2]), "r"(a[3]), "r"(b[0]), "r"(b[1]));
}

// ---------------------------------------------------------------------------
// tf32 mma.sync NT-GEMM: C[m,n] = sum_k A[m,k]*B[n,k].  Block 128 x NT.
// MODE 0: out[m*1024+n] = c + bias[n]                   (O-proj)
// MODE 1: out[((b*16+h)*1024+l)*64+d] = c + bias[n]     (Q/K proj)
// MODE 2: vT out[((b*16+h)*64+d)*1024+r] = c + bias[n]  (V proj)
// MODE 3: out[(z*1024+l)*1024+r] = c/8 + qd[z,l,clip]   (scores)
// MODE 4: out[(b*1024+l)*1024+h*64+n] = c               (P.V)
// ---------------------------------------------------------------------------
template<int MODE, int NT, int KTOT>
__global__ __launch_bounds__(256, 1) void gemm_mma(
    const float* __restrict__ Ag, const float* __restrict__ Bg,
    const float* __restrict__ aux, float* __restrict__ outg)
{
    constexpr int NC   = KTOT / 32;        // k-chunks
    constexpr int NTw  = NT / 32;          // n-tiles per warp (m16n8 tiles)
    constexpr int NNT  = NT / 8;           // n-tile regions per k-step
    constexpr int NB4  = NTw;              // B float4 loads per thread per chunk
    constexpr int AFL  = 4096;             // floats per A buffer (128x32)
    constexpr int BFL  = NT * 32;          // floats per B buffer
    constexpr int BUF  = AFL + BFL;

    extern __shared__ float sm[];

    const int tid  = threadIdx.x;
    const int wid  = tid >> 5, lane = tid & 31;
    const int wm   = wid >> 2, wn = wid & 3;
    const int g    = lane >> 2, tig = lane & 3;
    const int z    = blockIdx.z;
    const int m0   = blockIdx.y * 128, n0 = blockIdx.x * NT;

    const float* A; const float* B; size_t lda, ldb;
    if (MODE == 3)      { A = Ag + (size_t)z * SS * HDD; B = Bg + (size_t)z * SS * HDD; lda = HDD; ldb = HDD; }
    else if (MODE == 4) { A = Ag + (size_t)z * SS * SS;  B = Bg + (size_t)z * HDD * SS; lda = SS;  ldb = SS;  }
    else                { A = Ag; B = Bg; lda = KTOT; ldb = KTOT; }

    float c[4][NTw][4];
#pragma unroll
    for (int t = 0; t < 4; t++)
#pragma unroll
        for (int tn = 0; tn < NTw; tn++)
#pragma unroll
            for (int j = 0; j < 4; j++) c[t][tn][j] = 0.f;

    float4 aR[4], bR[NB4];

    // ---- helpers as lambdas ----
    auto ldgA = [&](int k0) {
#pragma unroll
        for (int j = 0; j < 4; j++) {
            int i = tid + j * 256, row = i >> 3, q = i & 7;
            aR[j] = *reinterpret_cast<const float4*>(A + (size_t)(m0 + row) * lda + k0 + q * 4);
        }
    };
    auto ldgB = [&](int k0) {
#pragma unroll
        for (int j = 0; j < NB4; j++) {
            int i = tid + j * 256, row = i >> 3, q = i & 7;
            bR[j] = *reinterpret_cast<const float4*>(B + (size_t)(n0 + row) * ldb + k0 + q * 4);
        }
    };
    auto stsA = [&](float* dA) {
#pragma unroll
        for (int j = 0; j < 4; j++) {
            int i = tid + j * 256, row = i >> 3, q = i & 7;
            int t = row >> 4, gg = row & 7, jb0 = (row >> 3) & 1;
            int s = q >> 1, jb1 = q & 1;
            int jreg = jb0 + 2 * jb1;
            float* base = dA + (s * 8 + t) * 128 + jreg;
            base[(gg * 4 + 0) * 4] = __uint_as_float(f2tf32(aR[j].x));
            base[(gg * 4 + 1) * 4] = __uint_as_float(f2tf32(aR[j].y));
            base[(gg * 4 + 2) * 4] = __uint_as_float(f2tf32(aR[j].z));
            base[(gg * 4 + 3) * 4] = __uint_as_float(f2tf32(aR[j].w));
        }
    };
    auto stsB = [&](float* dB) {
#pragma unroll
        for (int j = 0; j < NB4; j++) {
            int i = tid + j * 256, row = i >> 3, q = i & 7;
            int tn = row >> 3, gg = row & 7;
            int s = q >> 1, jb = q & 1;
            float* base = dB + (s * NNT + tn) * 64 + jb;
            base[(gg * 4 + 0) * 2] = __uint_as_float(f2tf32(bR[j].x));
            base[(gg * 4 + 1) * 2] = __uint_as_float(f2tf32(bR[j].y));
            base[(gg * 4 + 2) * 2] = __uint_as_float(f2tf32(bR[j].z));
            base[(gg * 4 + 3) * 2] = __uint_as_float(f2tf32(bR[j].w));
        }
    };
    auto compute = [&](const float* sA, const float* sB) {
#pragma unroll
        for (int s = 0; s < 4; s++) {
            uint32_t a[4][4];
#pragma unroll
            for (int t = 0; t < 4; t++) {
                uint4 v = *reinterpret_cast<const uint4*>(sA + (s * 8 + wm * 4 + t) * 128 + lane * 4);
                a[t][0] = v.x; a[t][1] = v.y; a[t][2] = v.z; a[t][3] = v.w;
            }
            uint32_t b[NTw][2];
#pragma unroll
            for (int tn = 0; tn < NTw; tn++) {
                uint2 v = *reinterpret_cast<const uint2*>(sB + (s * NNT + wn * NTw + tn) * 64 + lane * 2);
                b[tn][0] = v.x; b[tn][1] = v.y;
            }
#pragma unroll
            for (int t = 0; t < 4; t++)
#pragma unroll
                for (int tn = 0; tn < NTw; tn++) mma8(c[t][tn], a[t], b[tn]);
        }
    };

    // ---- pipelined mainloop ----
    ldgA(0); ldgB(0);
    stsA(sm); stsB(sm + AFL);
    __syncthreads();

    for (int ch = 0; ch < NC; ch++) {
        if (ch + 1 < NC) { ldgA((ch + 1) * 32); ldgB((ch + 1) * 32); }
        const float* sA = sm + (ch & 1) * BUF;
        compute(sA, sA + AFL);
        if (ch + 1 < NC) {
            float* dA = sm + ((ch + 1) & 1) * BUF;
            stsA(dA); stsB(dA + AFL);
            __syncthreads();
        }
    }

    // ---- epilogue (direct from fragments) ----
#pragma unroll
    for (int t = 0; t < 4; t++) {
        int r0 = m0 + wm * 64 + t * 16 + g;       // row for c0/c1
#pragma unroll
        for (int tn = 0; tn < NTw; tn++) {
            int cb = n0 + wn * (NT / 4) + tn * 8 + 2 * tig;
            float v00 = c[t][tn][0], v01 = c[t][tn][1];
            float v10 = c[t][tn][2], v11 = c[t][tn][3];

            if (MODE == 0) {
                float2 bb = *reinterpret_cast<const float2*>(aux + cb);
                float2 o0 = {v00 + bb.x, v01 + bb.y};
                float2 o1 = {v10 + bb.x, v11 + bb.y};
                *reinterpret_cast<float2*>(outg + (size_t)r0 * HIDN + cb) = o0;
                *reinterpret_cast<float2*>(outg + (size_t)(r0 + 8) * HIDN + cb) = o1;
            } else if (MODE == 1) {
                float2 bb = *reinterpret_cast<const float2*>(aux + cb);
                int h = cb >> 6, d0 = cb & 63;
#pragma unroll
                for (int rr = 0; rr < 2; rr++) {
                    int m = r0 + rr * 8;
                    int b = m >> 10, l = m & 1023;
                    float2 o = {(rr ? v10 : v00) + bb.x, (rr ? v11 : v01) + bb.y};
                    *reinterpret_cast<float2*>(
                        outg + ((size_t)(b * NHH + h) * SS + l) * HDD + d0) = o;
                }
            } else if (MODE == 2) {
                float2 bb = *reinterpret_cast<const float2*>(aux + cb);
                int h = cb >> 6, d0 = cb & 63;
#pragma unroll
                for (int rr = 0; rr < 2; rr++) {
                    int m = r0 + rr * 8;
                    int b = m >> 10, rt = m & 1023;
                    size_t base = ((size_t)(b * NHH + h) * HDD + d0) * SS + rt;
                    outg[base]      = (rr ? v10 : v00) + bb.x;
                    outg[base + SS] = (rr ? v11 : v01) + bb.y;
                }
            } else if (MODE == 3) {
#pragma unroll
                for (int rr = 0; rr < 2; rr++) {
                    int l = r0 + rr * 8;
                    const float* qdr = aux + ((size_t)z * SS + l) * NPOS;
                    int d0 = min(max(cb - l, -64), 8) + 64;
                    int d1 = min(max(cb + 1 - l, -64), 8) + 64;
                    float2 o = {(rr ? v10 : v00) * 0.125f + qdr[d0],
                                (rr ? v11 : v01) * 0.125f + qdr[d1]};
                    *reinterpret_cast<float2*>(outg + ((size_t)z * SS + l) * SS + cb) = o;
                }
            } else { // MODE 4
                int b = z >> 4, h = z & 15;
#pragma unroll
                for (int rr = 0; rr < 2; rr++) {
                    int l = r0 + rr * 8;
                    float2 o = {(rr ? v10 : v00), (rr ? v11 : v01)};
                    *reinterpret_cast<float2*>(
                        outg + ((size_t)(b * SS + l)) * HIDN + h * HDD + cb) = o;
                }
            }
        }
    }
}

// ---------------------------------------------------------------------------
// qd[row,p] = (1/8) * sum_d q[row,d] * emb[p,d]; 8 positions per thread
// ---------------------------------------------------------------------------
__global__ __launch_bounds__(256) void qd_kernel(
    const float* __restrict__ q, const float* __restrict__ emb, float* __restrict__ qd)
{
    __shared__ float se[NPOS * HDD];
    int tid = threadIdx.x;
    for (int i = tid; i < NPOS * HDD; i += 256) se[i] = emb[i];
    __syncthreads();

    int row = blockIdx.x * 256 + tid;
    int p0  = blockIdx.y * 8;
    const float4* qr = reinterpret_cast<const float4*>(q + (size_t)row * HDD);
    float acc[8] = {0.f, 0.f, 0.f, 0.f, 0.f, 0.f, 0.f, 0.f};
#pragma unroll
    for (int dq = 0; dq < 16; dq++) {
        float4 v = qr[dq];
#pragma unroll
        for (int j = 0; j < 8; j++) {
            if (p0 + j < NPOS) {
                const float* e = se + (p0 + j) * HDD + dq * 4;
                acc[j] = fmaf(v.x, e[0], fmaf(v.y, e[1], fmaf(v.z, e[2], fmaf(v.w, e[3], acc[j]))));
            }
        }
    }
    float* o = qd + (size_t)row * NPOS + p0;
#pragma unroll
    for (int j = 0; j < 8; j++)
        if (p0 + j < NPOS) o[j] = acc[j] * 0.125f;
}

// ---------------------------------------------------------------------------
// In-place row softmax over 1024 cols
// ---------------------------------------------------------------------------
__global__ __launch_bounds__(256) void softmax_kernel(float* __restrict__ probs)
{
    size_t row = blockIdx.x;
    float* p = probs + row * SS;
    int tid = threadIdx.x;
    float4 v = *reinterpret_cast<float4*>(p + tid * 4);

    float mx = fmaxf(fmaxf(v.x, v.y), fmaxf(v.z, v.w));
#pragma unroll
    for (int o = 16; o; o >>= 1) mx = fmaxf(mx, __shfl_xor_sync(0xffffffffu, mx, o));
    __shared__ float red[8];
    if ((tid & 31) == 0) red[tid >> 5] = mx;
    __syncthreads();
    mx = red[0];
#pragma unroll
    for (int w = 1; w < 8; w++) mx = fmaxf(mx, red[w]);
    __syncthreads();

    v.x = __expf(v.x - mx); v.y = __expf(v.y - mx);
    v.z = __expf(v.z - mx); v.w = __expf(v.w - mx);
    float s = v.x + v.y + v.z + v.w;
#pragma unroll
    for (int o = 16; o; o >>= 1) s += __shfl_xor_sync(0xffffffffu, s, o);
    if ((tid & 31) == 0) red[tid >> 5] = s;
    __syncthreads();
    s = red[0];
#pragma unroll
    for (int w = 1; w < 8; w++) s += red[w];

    float inv = 1.0f / s;
    v.x *= inv; v.y *= inv; v.z *= inv; v.w *= inv;
    *reinterpret_cast<float4*>(p + tid * 4) = v;
}

// ---------------------------------------------------------------------------
extern "C" void kernel_launch(void* const* d_in, const int* in_sizes, int n_in,
                              void* d_out, int out_size)
{
    const float* hid  = (const float*)d_in[0];
    const float* Wq   = (const float*)d_in[1];
    const float* bq   = (const float*)d_in[2];
    const float* Wk   = (const float*)d_in[3];
    const float* bk   = (const float*)d_in[4];
    const float* Wv   = (const float*)d_in[5];
    const float* bv   = (const float*)d_in[6];
    const float* Wo   = (const float*)d_in[7];
    const float* bo   = (const float*)d_in[8];
    const float* demb = (const float*)d_in[9];

    float* out   = (float*)d_out;
    float* probs = out + (size_t)MTOT * HIDN;

    float *q, *k, *v, *ctx, *qd;
    cudaGetSymbolAddress((void**)&q,   g_q);
    cudaGetSymbolAddress((void**)&k,   g_k);
    cudaGetSymbolAddress((void**)&v,   g_v);
    cudaGetSymbolAddress((void**)&ctx, g_ctx);
    cudaGetSymbolAddress((void**)&qd,  g_qd);

    const int SM_128 = 2 * (4096 + 128 * 32) * 4;   // 65536
    const int SM_64  = 2 * (4096 + 64 * 32) * 4;    // 49152

    cudaFuncSetAttribute(gemm_mma<0,128,1024>, cudaFuncAttributeMaxDynamicSharedMemorySize, SM_128);
    cudaFuncSetAttribute(gemm_mma<1,128,1024>, cudaFuncAttributeMaxDynamicSharedMemorySize, SM_128);
    cudaFuncSetAttribute(gemm_mma<2,128,1024>, cudaFuncAttributeMaxDynamicSharedMemorySize, SM_128);
    cudaFuncSetAttribute(gemm_mma<3,128,64>,   cudaFuncAttributeMaxDynamicSharedMemorySize, SM_128);
    cudaFuncSetAttribute(gemm_mma<4,64,1024>,  cudaFuncAttributeMaxDynamicSharedMemorySize, SM_64);

    dim3 gproj(8, 32);
    gemm_mma<1,128,1024><<<gproj, 256, SM_128>>>(hid, Wq, bq, q);
    gemm_mma<1,128,1024><<<gproj, 256, SM_128>>>(hid, Wk, bk, k);
    gemm_mma<2,128,1024><<<gproj, 256, SM_128>>>(hid, Wv, bv, v);

    qd_kernel<<<dim3(256, 10), 256>>>(q, demb, qd);

    gemm_mma<3,128,64><<<dim3(8, 8, BHT), 256, SM_128>>>(q, k, qd, probs);

    softmax_kernel<<<BHT * SS, 256>>>(probs);

    gemm_mma<4,64,1024><<<dim3(1, 8, BHT), 256, SM_64>>>(probs, v, (const float*)0, ctx);

    gemm_mma<0,128,1024><<<gproj, 256, SM_128>>>(ctx, Wo, bo, out);
}